// round 1
// baseline (speedup 1.0000x reference)
#include <cuda_runtime.h>

#define B_   16
#define C_   512
#define NH   8
#define HD   64
#define N_   1024
#define G_   32
#define CPG  16
#define EPSV 1e-5f

// Scratch (device globals — no allocation allowed)
__device__ float g_hn[(size_t)B_ * C_ * N_];            // normalized input  [b][c][n]
__device__ float g_qkv[(size_t)3 * B_ * NH * N_ * HD];  // [s][b][h][n][d]
__device__ float g_obuf[(size_t)B_ * N_ * C_];          // attention out [b][n][c]

// ---------------------------------------------------------------------------
// 1) GroupNorm: one block per (b, group). Group data is contiguous: 16*1024 f32
// ---------------------------------------------------------------------------
__global__ __launch_bounds__(256) void gn_kernel(const float* __restrict__ x,
                                                 const float* __restrict__ w,
                                                 const float* __restrict__ bb) {
    int bg = blockIdx.x;  // b*32 + g
    const float4* x4 = (const float4*)(x + (size_t)bg * CPG * N_);
    float4* h4 = (float4*)(g_hn + (size_t)bg * CPG * N_);
    int tid = threadIdx.x;

    float s = 0.f, s2 = 0.f;
    #pragma unroll 4
    for (int i = tid; i < 4096; i += 256) {
        float4 v = x4[i];
        s  += v.x + v.y + v.z + v.w;
        s2 += v.x*v.x + v.y*v.y + v.z*v.z + v.w*v.w;
    }
    __shared__ float rs[256], rs2[256];
    rs[tid] = s; rs2[tid] = s2;
    __syncthreads();
    for (int off = 128; off > 0; off >>= 1) {
        if (tid < off) { rs[tid] += rs[tid+off]; rs2[tid] += rs2[tid+off]; }
        __syncthreads();
    }
    float mean = rs[0] * (1.f/16384.f);
    float var  = rs2[0] * (1.f/16384.f) - mean*mean;
    float rstd = rsqrtf(var + EPSV);
    int g = bg & (G_-1);

    #pragma unroll 4
    for (int i = tid; i < 4096; i += 256) {
        int c = g*CPG + (i >> 8);          // 256 float4 per channel
        float sc = rstd * w[c];
        float sh = bb[c] - mean * sc;
        float4 v = x4[i];
        v.x = v.x*sc + sh; v.y = v.y*sc + sh;
        v.z = v.z*sc + sh; v.w = v.w*sc + sh;
        h4[i] = v;
    }
}

// ---------------------------------------------------------------------------
// 2) QKV GEMM per batch: [1536 x 512] @ [512 x 1024], scatter to [s][b][h][n][d]
// ---------------------------------------------------------------------------
__global__ __launch_bounds__(256) void qkv_kernel(const float* __restrict__ W,
                                                  const float* __restrict__ bias) {
    int n0 = blockIdx.x * 64, m0 = blockIdx.y * 64, b = blockIdx.z;
    const float* Bm = g_hn + (size_t)b * C_ * N_;

    __shared__ float As[16][68];
    __shared__ float Bs[16][68];

    int tid  = threadIdx.x;
    int arow = tid >> 2,  acol = (tid & 3) * 4;
    int brow = tid >> 4,  bcol = (tid & 15) * 4;
    int ty   = tid >> 4,  tx   = tid & 15;

    float acc[4][4] = {};

    for (int k0 = 0; k0 < C_; k0 += 16) {
        float4 av = *(const float4*)&W[(size_t)(m0 + arow) * C_ + k0 + acol];
        As[acol+0][arow] = av.x; As[acol+1][arow] = av.y;
        As[acol+2][arow] = av.z; As[acol+3][arow] = av.w;
        float4 bv = *(const float4*)&Bm[(size_t)(k0 + brow) * N_ + n0 + bcol];
        *(float4*)&Bs[brow][bcol] = bv;
        __syncthreads();
        #pragma unroll
        for (int kk = 0; kk < 16; kk++) {
            float4 a  = *(const float4*)&As[kk][ty*4];
            float4 b4 = *(const float4*)&Bs[kk][tx*4];
            float avr[4] = {a.x, a.y, a.z, a.w};
            float bvr[4] = {b4.x, b4.y, b4.z, b4.w};
            #pragma unroll
            for (int i = 0; i < 4; i++)
                #pragma unroll
                for (int j = 0; j < 4; j++)
                    acc[i][j] += avr[i] * bvr[j];
        }
        __syncthreads();
    }

    #pragma unroll
    for (int i = 0; i < 4; i++) {
        int o = m0 + ty*4 + i;
        int s = o >> 9, r = o & 511, head = r >> 6, d = r & 63;
        float bi = bias[o];
        size_t base = ((size_t)s * B_ + b) * NH + head;   // (s,b,h)
        base = base * N_;
        #pragma unroll
        for (int j = 0; j < 4; j++) {
            int n = n0 + tx*4 + j;
            g_qkv[(base + n) * HD + d] = acc[i][j] + bi;
        }
    }
}

// ---------------------------------------------------------------------------
// 3) Flash attention: block = 64 query rows of one (b,h); thread = 1 q row.
//    KV tiles of 32 staged in smem; online softmax; fp32 throughout.
// ---------------------------------------------------------------------------
#define KVT 32
__global__ __launch_bounds__(64) void attn_kernel() {
    int bh = blockIdx.x;            // b*8 + h
    int q0 = blockIdx.y * 64;
    int tid = threadIdx.x;

    const float* qbase = g_qkv + ((size_t)(0 * B_ * NH + bh)) * N_ * HD;
    const float* kbase = g_qkv + ((size_t)(1 * B_ * NH + bh)) * N_ * HD;
    const float* vbase = g_qkv + ((size_t)(2 * B_ * NH + bh)) * N_ * HD;

    __shared__ float Ks[KVT * HD];
    __shared__ float Vs[KVT * HD];

    float q[64], acc[64];
    const float4* q4g = (const float4*)(qbase + (size_t)(q0 + tid) * HD);
    const float scale = 0.125f;  // 64^-0.5
    #pragma unroll
    for (int i = 0; i < 16; i++) {
        float4 v = q4g[i];
        q[4*i+0] = v.x * scale; q[4*i+1] = v.y * scale;
        q[4*i+2] = v.z * scale; q[4*i+3] = v.w * scale;
    }
    #pragma unroll
    for (int d = 0; d < 64; d++) acc[d] = 0.f;
    float m = -3.4e38f, l = 0.f;

    #pragma unroll 1
    for (int t = 0; t < N_ / KVT; t++) {
        const float4* kt = (const float4*)(kbase + (size_t)t * KVT * HD);
        const float4* vt = (const float4*)(vbase + (size_t)t * KVT * HD);
        float4* kw = (float4*)Ks;
        float4* vw = (float4*)Vs;
        __syncthreads();
        #pragma unroll
        for (int r = 0; r < 8; r++) {       // 512 float4 / 64 threads
            kw[r*64 + tid] = kt[r*64 + tid];
            vw[r*64 + tid] = vt[r*64 + tid];
        }
        __syncthreads();

        float s[KVT];
        #pragma unroll
        for (int j = 0; j < KVT; j++) s[j] = 0.f;

        const float4* K4 = (const float4*)Ks;
        #pragma unroll
        for (int d4 = 0; d4 < 16; d4++) {
            float qx = q[4*d4+0], qy = q[4*d4+1], qz = q[4*d4+2], qw = q[4*d4+3];
            #pragma unroll
            for (int j = 0; j < KVT; j++) {
                float4 kv = K4[j*16 + d4];
                s[j] += qx*kv.x + qy*kv.y + qz*kv.z + qw*kv.w;
            }
        }

        float tmax = s[0];
        #pragma unroll
        for (int j = 1; j < KVT; j++) tmax = fmaxf(tmax, s[j]);
        float mn = fmaxf(m, tmax);
        float corr = __expf(m - mn);
        l *= corr;
        #pragma unroll
        for (int d = 0; d < 64; d++) acc[d] *= corr;
        float ls = 0.f;
        #pragma unroll
        for (int j = 0; j < KVT; j++) {
            float p = __expf(s[j] - mn);
            ls += p;
            s[j] = p;
        }
        l += ls;
        m = mn;

        const float4* V4 = (const float4*)Vs;
        #pragma unroll
        for (int j = 0; j < KVT; j++) {
            float p = s[j];
            #pragma unroll
            for (int d4 = 0; d4 < 16; d4++) {
                float4 vv = V4[j*16 + d4];
                acc[4*d4+0] += p * vv.x; acc[4*d4+1] += p * vv.y;
                acc[4*d4+2] += p * vv.z; acc[4*d4+3] += p * vv.w;
            }
        }
    }

    float inv = 1.f / l;
    int b = bh >> 3, h = bh & 7;
    float4* o4 = (float4*)(g_obuf + ((size_t)b * N_ + q0 + tid) * C_ + h * HD);
    #pragma unroll
    for (int i = 0; i < 16; i++) {
        float4 r;
        r.x = acc[4*i+0]*inv; r.y = acc[4*i+1]*inv;
        r.z = acc[4*i+2]*inv; r.w = acc[4*i+3]*inv;
        o4[i] = r;
    }
}

// ---------------------------------------------------------------------------
// 4) Proj GEMM + bias + residual: out[b][o][n] = proj_w @ obuf[b][:,n] + b + x
//    obuf is [b][n][c] so K-dim loads are contiguous.
// ---------------------------------------------------------------------------
__global__ __launch_bounds__(256) void proj_kernel(const float* __restrict__ W,
                                                   const float* __restrict__ bias,
                                                   const float* __restrict__ x,
                                                   float* __restrict__ out) {
    int n0 = blockIdx.x * 64, m0 = blockIdx.y * 64, b = blockIdx.z;
    const float* Bm = g_obuf + (size_t)b * N_ * C_;   // [n][c]

    __shared__ float As[16][68];
    __shared__ float Bs[16][68];

    int tid  = threadIdx.x;
    int arow = tid >> 2, acol = (tid & 3) * 4;
    int jrow = tid >> 2, kcol = (tid & 3) * 4;   // B tile: j = n index, k along c
    int ty   = tid >> 4, tx   = tid & 15;

    float acc[4][4] = {};

    for (int k0 = 0; k0 < C_; k0 += 16) {
        float4 av = *(const float4*)&W[(size_t)(m0 + arow) * C_ + k0 + acol];
        As[acol+0][arow] = av.x; As[acol+1][arow] = av.y;
        As[acol+2][arow] = av.z; As[acol+3][arow] = av.w;
        float4 bv = *(const float4*)&Bm[(size_t)(n0 + jrow) * C_ + k0 + kcol];
        Bs[kcol+0][jrow] = bv.x; Bs[kcol+1][jrow] = bv.y;
        Bs[kcol+2][jrow] = bv.z; Bs[kcol+3][jrow] = bv.w;
        __syncthreads();
        #pragma unroll
        for (int kk = 0; kk < 16; kk++) {
            float4 a  = *(const float4*)&As[kk][ty*4];
            float4 b4 = *(const float4*)&Bs[kk][tx*4];
            float avr[4] = {a.x, a.y, a.z, a.w};
            float bvr[4] = {b4.x, b4.y, b4.z, b4.w};
            #pragma unroll
            for (int i = 0; i < 4; i++)
                #pragma unroll
                for (int j = 0; j < 4; j++)
                    acc[i][j] += avr[i] * bvr[j];
        }
        __syncthreads();
    }

    #pragma unroll
    for (int i = 0; i < 4; i++) {
        int o = m0 + ty*4 + i;
        float bi = bias[o];
        size_t row = ((size_t)b * C_ + o) * N_ + n0 + tx*4;
        float4 xv = *(const float4*)&x[row];
        float4 r;
        r.x = acc[i][0] + bi + xv.x;
        r.y = acc[i][1] + bi + xv.y;
        r.z = acc[i][2] + bi + xv.z;
        r.w = acc[i][3] + bi + xv.w;
        *(float4*)&out[row] = r;
    }
}

// ---------------------------------------------------------------------------
extern "C" void kernel_launch(void* const* d_in, const int* in_sizes, int n_in,
                              void* d_out, int out_size) {
    const float* x      = (const float*)d_in[0];
    const float* norm_w = (const float*)d_in[1];
    const float* norm_b = (const float*)d_in[2];
    const float* qkv_w  = (const float*)d_in[3];
    const float* qkv_b  = (const float*)d_in[4];
    const float* proj_w = (const float*)d_in[5];
    const float* proj_b = (const float*)d_in[6];
    float* out = (float*)d_out;

    gn_kernel<<<B_ * G_, 256>>>(x, norm_w, norm_b);
    qkv_kernel<<<dim3(N_/64, (3*C_)/64, B_), 256>>>(qkv_w, qkv_b);
    attn_kernel<<<dim3(B_*NH, N_/64), 64>>>();
    proj_kernel<<<dim3(N_/64, C_/64, B_), 256>>>(proj_w, proj_b, x, out);
}